// round 1
// baseline (speedup 1.0000x reference)
#include <cuda_runtime.h>
#include <cstdint>

#define N_NODES 100000
#define E_EDGES 1600000
#define F       128
#define C_OUT   64

// ---- device scratch (static allocation; no cudaMalloc allowed) ----
__device__ float g_deg[N_NODES];
__device__ float g_dinv[N_NODES];
__device__ float g_xws[(size_t)N_NODES * F];   // dinv[i] * (x @ W)[i]  (51.2 MB)
__device__ float g_s[(size_t)N_NODES * F];     // scatter accumulator    (51.2 MB)
__device__ float g_bfc2[C_OUT];                // b_fc + W_fc @ b_gcn

// -------------------- degree --------------------
__global__ void k_init_deg(int n) {
    int i = blockIdx.x * blockDim.x + threadIdx.x;
    if (i < n) g_deg[i] = 1.0f;   // self-loop
}

__global__ void k_edge_deg(const int* __restrict__ col, int e) {
    int i = blockIdx.x * blockDim.x + threadIdx.x;
    if (i < e) atomicAdd(&g_deg[col[i]], 1.0f);   // compiles to RED (no return use)
}

__global__ void k_dinv(int n) {
    int i = blockIdx.x * blockDim.x + threadIdx.x;
    if (i < n) g_dinv[i] = rsqrtf(g_deg[i]);
}

// -------------------- XW GEMM: xws = dinv * (x @ W_gcn); s init = xws --------------------
// tile: 32 rows x 128 cols per block, 256 threads, each thread 4 rows x 4 cols
__global__ void k_xw(const float* __restrict__ x, const float* __restrict__ W, int n) {
    extern __shared__ float sh[];
    float* Wsm = sh;            // 128*128 floats = 64 KB
    float* Xsm = sh + F * F;    // 32*128  floats = 16 KB

    int t = threadIdx.x;
    // load W (row-major [k][c]) into smem
    for (int i = t; i < (F * F) / 4; i += 256)
        ((float4*)Wsm)[i] = ((const float4*)W)[i];

    int base = blockIdx.x * 32;
    // load 32-row x tile (zero-pad past n)
    for (int i = t; i < 32 * 32; i += 256) {  // 32 rows x 32 float4
        int rr = i >> 5, cc = i & 31;
        int r = base + rr;
        float4 v = make_float4(0.f, 0.f, 0.f, 0.f);
        if (r < n) v = ((const float4*)x)[(size_t)r * 32 + cc];
        ((float4*)Xsm)[i] = v;
    }
    __syncthreads();

    int tx = t & 31;          // col group
    int ty = t >> 5;          // row group (0..7)
    int c0 = tx * 4;

    float acc[4][4];
#pragma unroll
    for (int i = 0; i < 4; ++i)
#pragma unroll
        for (int j = 0; j < 4; ++j) acc[i][j] = 0.f;

#pragma unroll 4
    for (int k = 0; k < F; ++k) {
        float4 w = *(const float4*)&Wsm[k * F + c0];
#pragma unroll
        for (int i = 0; i < 4; ++i) {
            float xv = Xsm[(ty * 4 + i) * F + k];
            acc[i][0] = fmaf(xv, w.x, acc[i][0]);
            acc[i][1] = fmaf(xv, w.y, acc[i][1]);
            acc[i][2] = fmaf(xv, w.z, acc[i][2]);
            acc[i][3] = fmaf(xv, w.w, acc[i][3]);
        }
    }

#pragma unroll
    for (int i = 0; i < 4; ++i) {
        int r = base + ty * 4 + i;
        if (r < n) {
            float dv = g_dinv[r];
            float4 v;
            v.x = dv * acc[i][0];
            v.y = dv * acc[i][1];
            v.z = dv * acc[i][2];
            v.w = dv * acc[i][3];
            *(float4*)&g_xws[(size_t)r * F + c0] = v;
            *(float4*)&g_s[(size_t)r * F + c0]   = v;   // self-loop init
        }
    }
}

// -------------------- edge scatter: s[col] += xws[row] --------------------
// one warp per edge, lane handles float4
__global__ void k_scatter(const int* __restrict__ ei, int e) {
    int gw = (blockIdx.x * blockDim.x + threadIdx.x) >> 5;
    int lane = threadIdx.x & 31;
    if (gw >= e) return;
    int row = __ldg(&ei[gw]);
    int col = __ldg(&ei[e + gw]);
    float4 v = *(const float4*)&g_xws[(size_t)row * F + lane * 4];
    float* p = &g_s[(size_t)col * F + lane * 4];
    asm volatile("red.global.add.v4.f32 [%0], {%1, %2, %3, %4};"
                 :: "l"(p), "f"(v.x), "f"(v.y), "f"(v.z), "f"(v.w) : "memory");
}

// -------------------- fused bias: bfc2 = b_fc + W_fc @ b_gcn --------------------
__global__ void k_bfc2(const float* __restrict__ Wfc, const float* __restrict__ bgcn,
                       const float* __restrict__ bfc) {
    int c = threadIdx.x;
    if (c < C_OUT) {
        float s = bfc[c];
        for (int k = 0; k < F; ++k) s = fmaf(bgcn[k], Wfc[c * F + k], s);
        g_bfc2[c] = s;
    }
}

// -------------------- output GEMM: out = dinv * (s @ W_fc^T) + bfc2 --------------------
// tile: 32 rows x 64 cols per block, 256 threads, each thread 2 rows x 4 cols
__global__ void k_out(const float* __restrict__ Wfc, float* __restrict__ out, int n) {
    extern __shared__ float sh[];
    float* Wt  = sh;              // [k][c] transposed: 128*64 = 32 KB
    float* Ssm = sh + F * C_OUT;  // 32*128 = 16 KB

    int t = threadIdx.x;
    // transpose W_fc [c][k] -> Wt [k][c]
    for (int i = t; i < C_OUT * F; i += 256) {
        int c = i / F, k = i % F;
        Wt[k * C_OUT + c] = Wfc[i];
    }

    int base = blockIdx.x * 32;
    for (int i = t; i < 32 * 32; i += 256) {
        int rr = i >> 5, cc = i & 31;
        int r = base + rr;
        float4 v = make_float4(0.f, 0.f, 0.f, 0.f);
        if (r < n) v = ((const float4*)g_s)[(size_t)r * 32 + cc];
        ((float4*)Ssm)[i] = v;
    }
    __syncthreads();

    int tx = t & 15;          // col group: c0 = tx*4
    int ty = t >> 4;          // row group (0..15), 2 rows each
    int c0 = tx * 4;

    float acc[2][4];
#pragma unroll
    for (int i = 0; i < 2; ++i)
#pragma unroll
        for (int j = 0; j < 4; ++j) acc[i][j] = 0.f;

#pragma unroll 4
    for (int k = 0; k < F; ++k) {
        float4 w = *(const float4*)&Wt[k * C_OUT + c0];
#pragma unroll
        for (int i = 0; i < 2; ++i) {
            float xv = Ssm[(ty * 2 + i) * F + k];
            acc[i][0] = fmaf(xv, w.x, acc[i][0]);
            acc[i][1] = fmaf(xv, w.y, acc[i][1]);
            acc[i][2] = fmaf(xv, w.z, acc[i][2]);
            acc[i][3] = fmaf(xv, w.w, acc[i][3]);
        }
    }

    float4 b = *(const float4*)&g_bfc2[c0];
#pragma unroll
    for (int i = 0; i < 2; ++i) {
        int r = base + ty * 2 + i;
        if (r < n) {
            float dv = g_dinv[r];
            float4 v;
            v.x = fmaf(dv, acc[i][0], b.x);
            v.y = fmaf(dv, acc[i][1], b.y);
            v.z = fmaf(dv, acc[i][2], b.z);
            v.w = fmaf(dv, acc[i][3], b.w);
            *(float4*)&out[(size_t)r * C_OUT + c0] = v;
        }
    }
}

// -------------------- launch --------------------
extern "C" void kernel_launch(void* const* d_in, const int* in_sizes, int n_in,
                              void* d_out, int out_size) {
    const float* x    = (const float*)d_in[0];
    const int*   ei   = (const int*)d_in[1];
    const float* Wgcn = (const float*)d_in[2];
    const float* bgcn = (const float*)d_in[3];
    const float* Wfc  = (const float*)d_in[4];
    const float* bfc  = (const float*)d_in[5];
    float* out = (float*)d_out;

    int n = in_sizes[0] / F;       // 100000
    int e = in_sizes[1] / 2;       // 1600000

    static bool attr_set = false;
    if (!attr_set) {
        cudaFuncSetAttribute(k_xw,  cudaFuncAttributeMaxDynamicSharedMemorySize, (F*F + 32*F) * 4);
        cudaFuncSetAttribute(k_out, cudaFuncAttributeMaxDynamicSharedMemorySize, (F*C_OUT + 32*F) * 4);
        attr_set = true;
    }

    int nb = (n + 255) / 256;
    k_init_deg<<<nb, 256>>>(n);
    k_edge_deg<<<(e + 255) / 256, 256>>>(ei + e, e);   // col = target index
    k_dinv<<<nb, 256>>>(n);

    int gemm_blocks = (n + 31) / 32;
    k_xw<<<gemm_blocks, 256, (F*F + 32*F) * 4>>>(x, Wgcn, n);

    int warps_needed = e;                               // one warp per edge
    int sblocks = (warps_needed * 32 + 255) / 256;
    k_scatter<<<sblocks, 256>>>(ei, e);

    k_bfc2<<<1, 64>>>(Wfc, bgcn, bfc);
    k_out<<<gemm_blocks, 256, (F*C_OUT + 32*F) * 4>>>(Wfc, out, n);
}

// round 2
// speedup vs baseline: 2.4263x; 2.4263x over previous
#include <cuda_runtime.h>
#include <cstdint>

#define N_NODES 100000
#define E_EDGES 1600000
#define F       128
#define C_OUT   64

// ---- device scratch ----
__device__ float g_deg[N_NODES];
__device__ float g_dinv[N_NODES];
__device__ float g_wcomb[F * C_OUT];             // W_gcn @ W_fc^T  [128][64]
__device__ float g_xws[(size_t)N_NODES * C_OUT]; // dinv * (x @ Wcomb)  (25.6 MB)
__device__ float g_s[(size_t)N_NODES * C_OUT];   // scatter accumulator (25.6 MB)
__device__ float g_bfc2[C_OUT];                  // b_fc + W_fc @ b_gcn

// -------------------- degree --------------------
__global__ void k_init_deg(int n) {
    int i = blockIdx.x * blockDim.x + threadIdx.x;
    if (i < n) g_deg[i] = 1.0f;   // self-loop
}

__global__ void k_edge_deg(const int* __restrict__ col, int e) {
    int i = blockIdx.x * blockDim.x + threadIdx.x;
    if (i < e) atomicAdd(&g_deg[col[i]], 1.0f);   // RED (no return use)
}

__global__ void k_dinv(int n) {
    int i = blockIdx.x * blockDim.x + threadIdx.x;
    if (i < n) g_dinv[i] = rsqrtf(g_deg[i]);
}

// -------------------- Wcomb = W_gcn @ W_fc^T --------------------
// Wcomb[k][c] = sum_j W_gcn[k][j] * W_fc[c][j]
__global__ void k_wcomb(const float* __restrict__ Wg, const float* __restrict__ Wfc) {
    int idx = blockIdx.x * blockDim.x + threadIdx.x;   // 128*64 = 8192
    int k = idx >> 6, c = idx & 63;
    float s = 0.f;
#pragma unroll 4
    for (int j = 0; j < F; ++j)
        s = fmaf(Wg[k * F + j], Wfc[c * F + j], s);
    g_wcomb[k * C_OUT + c] = s;
}

// -------------------- bfc2 = b_fc + W_fc @ b_gcn --------------------
__global__ void k_bfc2(const float* __restrict__ Wfc, const float* __restrict__ bgcn,
                       const float* __restrict__ bfc) {
    int c = threadIdx.x;
    if (c < C_OUT) {
        float s = bfc[c];
        for (int k = 0; k < F; ++k) s = fmaf(bgcn[k], Wfc[c * F + k], s);
        g_bfc2[c] = s;
    }
}

// -------------------- GEMM: xws = dinv * (x @ Wcomb); s init = xws --------------------
// tile: 64 rows x 64 cols per block, 256 threads, each thread 4 rows x 4 cols
__global__ void k_xw(const float* __restrict__ x, int n) {
    extern __shared__ float sh[];
    float* Wsm = sh;               // 128*64 floats = 32 KB  [k][c]
    float* Xsm = sh + F * C_OUT;   // 64*128 floats = 32 KB  [r][k]

    int t = threadIdx.x;
    // load Wcomb into smem
    for (int i = t; i < (F * C_OUT) / 4; i += 256)
        ((float4*)Wsm)[i] = ((const float4*)g_wcomb)[i];

    int base = blockIdx.x * 64;
    // load 64-row x tile (zero-pad past n)
    for (int i = t; i < 64 * 32; i += 256) {   // 64 rows x 32 float4
        int rr = i >> 5, cc = i & 31;
        int r = base + rr;
        float4 v = make_float4(0.f, 0.f, 0.f, 0.f);
        if (r < n) v = ((const float4*)x)[(size_t)r * 32 + cc];
        ((float4*)Xsm)[i] = v;
    }
    __syncthreads();

    int tx = t & 15;           // col group: c0 = tx*4
    int ty = t >> 4;           // row group (0..15), rows ty*4..ty*4+3
    int c0 = tx * 4;

    float acc[4][4];
#pragma unroll
    for (int i = 0; i < 4; ++i)
#pragma unroll
        for (int j = 0; j < 4; ++j) acc[i][j] = 0.f;

#pragma unroll 4
    for (int k = 0; k < F; ++k) {
        float4 w = *(const float4*)&Wsm[k * C_OUT + c0];
#pragma unroll
        for (int i = 0; i < 4; ++i) {
            float xv = Xsm[(ty * 4 + i) * F + k];
            acc[i][0] = fmaf(xv, w.x, acc[i][0]);
            acc[i][1] = fmaf(xv, w.y, acc[i][1]);
            acc[i][2] = fmaf(xv, w.z, acc[i][2]);
            acc[i][3] = fmaf(xv, w.w, acc[i][3]);
        }
    }

#pragma unroll
    for (int i = 0; i < 4; ++i) {
        int r = base + ty * 4 + i;
        if (r < n) {
            float dv = g_dinv[r];
            float4 v;
            v.x = dv * acc[i][0];
            v.y = dv * acc[i][1];
            v.z = dv * acc[i][2];
            v.w = dv * acc[i][3];
            *(float4*)&g_xws[(size_t)r * C_OUT + c0] = v;
            *(float4*)&g_s[(size_t)r * C_OUT + c0]   = v;   // self-loop init
        }
    }
}

// -------------------- edge scatter: s[col] += xws[row] --------------------
// 16 threads per edge, each handles one float4 (64 floats = 256B per edge)
__global__ void k_scatter(const int* __restrict__ ei, int e) {
    int gt = blockIdx.x * blockDim.x + threadIdx.x;
    int edge = gt >> 4;
    int lane = gt & 15;
    if (edge >= e) return;
    int row = __ldg(&ei[edge]);
    int col = __ldg(&ei[e + edge]);
    float4 v = *(const float4*)&g_xws[(size_t)row * C_OUT + lane * 4];
    float* p = &g_s[(size_t)col * C_OUT + lane * 4];
    asm volatile("red.global.add.v4.f32 [%0], {%1, %2, %3, %4};"
                 :: "l"(p), "f"(v.x), "f"(v.y), "f"(v.z), "f"(v.w) : "memory");
}

// -------------------- final: out = dinv * s + bfc2 --------------------
__global__ void k_final(float* __restrict__ out, int n) {
    int i = blockIdx.x * blockDim.x + threadIdx.x;   // over n*16 float4s
    if (i >= n * 16) return;
    int r = i >> 4, c4 = i & 15;
    float dv = g_dinv[r];
    float4 s = ((const float4*)g_s)[i];
    float4 b = ((const float4*)g_bfc2)[c4];
    float4 o;
    o.x = fmaf(dv, s.x, b.x);
    o.y = fmaf(dv, s.y, b.y);
    o.z = fmaf(dv, s.z, b.z);
    o.w = fmaf(dv, s.w, b.w);
    ((float4*)out)[i] = o;
}

// -------------------- launch --------------------
extern "C" void kernel_launch(void* const* d_in, const int* in_sizes, int n_in,
                              void* d_out, int out_size) {
    const float* x    = (const float*)d_in[0];
    const int*   ei   = (const int*)d_in[1];
    const float* Wgcn = (const float*)d_in[2];
    const float* bgcn = (const float*)d_in[3];
    const float* Wfc  = (const float*)d_in[4];
    const float* bfc  = (const float*)d_in[5];
    float* out = (float*)d_out;

    int n = in_sizes[0] / F;       // 100000
    int e = in_sizes[1] / 2;       // 1600000

    static bool attr_set = false;
    if (!attr_set) {
        cudaFuncSetAttribute(k_xw, cudaFuncAttributeMaxDynamicSharedMemorySize,
                             (F * C_OUT + 64 * F) * 4);
        attr_set = true;
    }

    int nb = (n + 255) / 256;
    k_init_deg<<<nb, 256>>>(n);
    k_edge_deg<<<(e + 255) / 256, 256>>>(ei + e, e);
    k_dinv<<<nb, 256>>>(n);

    k_wcomb<<<(F * C_OUT) / 256, 256>>>(Wgcn, Wfc);
    k_bfc2<<<1, 64>>>(Wfc, bgcn, bfc);

    int gemm_blocks = (n + 63) / 64;
    k_xw<<<gemm_blocks, 256, (F * C_OUT + 64 * F) * 4>>>(x, n);

    int sthreads = e * 16;
    k_scatter<<<(sthreads + 255) / 256, 256>>>(ei, e);

    k_final<<<(n * 16 + 255) / 256, 256>>>(out, n);
}

// round 3
// speedup vs baseline: 2.6155x; 1.0780x over previous
#include <cuda_runtime.h>
#include <cstdint>

#define N_NODES 100000
#define E_EDGES 1600000
#define F       128
#define C_OUT   64

// ---- device scratch ----
__device__ float g_deg[N_NODES];
__device__ float g_dinv[N_NODES];
__device__ float g_wcomb[F * C_OUT];             // W_gcn @ W_fc^T  [128][64]
__device__ float g_xws[(size_t)N_NODES * C_OUT]; // dinv * (x @ Wcomb)  (25.6 MB)
__device__ float g_s[(size_t)N_NODES * C_OUT];   // scatter accumulator (25.6 MB)
__device__ float g_bfc2[C_OUT];                  // b_fc + W_fc @ b_gcn

// ==================== fused setup ====================
// blocks [0, NB_INIT)            : g_deg = 1.0
// blocks [NB_INIT, NB_INIT+1024) : wcomb, 1 warp per output, coalesced + shfl
// block  NB_INIT+1024            : bfc2
#define NB_INIT ((N_NODES + 255) / 256)

__global__ void k_setup(const float* __restrict__ Wg, const float* __restrict__ Wfc,
                        const float* __restrict__ bgcn, const float* __restrict__ bfc,
                        int n) {
    int b = blockIdx.x;
    int t = threadIdx.x;
    if (b < NB_INIT) {
        int i = b * 256 + t;
        if (i < n) g_deg[i] = 1.0f;   // self-loop
        return;
    }
    int lane = t & 31;
    int w = t >> 5;
    if (b < NB_INIT + 1024) {
        // wcomb[k][c] = sum_j Wg[k][j] * Wfc[c][j];  8 warps/block, 1 output/warp
        int idx = (b - NB_INIT) * 8 + w;      // 0..8191
        int k = idx >> 6, c = idx & 63;
        const float* wg = Wg + k * F;
        const float* wf = Wfc + c * F;
        float s = wg[lane] * wf[lane];
        s = fmaf(wg[lane + 32], wf[lane + 32], s);
        s = fmaf(wg[lane + 64], wf[lane + 64], s);
        s = fmaf(wg[lane + 96], wf[lane + 96], s);
#pragma unroll
        for (int o = 16; o > 0; o >>= 1) s += __shfl_xor_sync(0xffffffffu, s, o);
        if (lane == 0) g_wcomb[idx] = s;
        return;
    }
    // bfc2: 8 warps, 8 outputs each
#pragma unroll
    for (int cc = 0; cc < 8; ++cc) {
        int c = w * 8 + cc;
        const float* wf = Wfc + c * F;
        float s = bgcn[lane] * wf[lane];
        s = fmaf(bgcn[lane + 32], wf[lane + 32], s);
        s = fmaf(bgcn[lane + 64], wf[lane + 64], s);
        s = fmaf(bgcn[lane + 96], wf[lane + 96], s);
#pragma unroll
        for (int o = 16; o > 0; o >>= 1) s += __shfl_xor_sync(0xffffffffu, s, o);
        if (lane == 0) g_bfc2[c] = s + bfc[c];
    }
}

// ==================== degree (edges) ====================
__global__ void k_edge_deg(const int* __restrict__ col, int e) {
    int i = blockIdx.x * blockDim.x + threadIdx.x;
    if (i < e) atomicAdd(&g_deg[col[i]], 1.0f);   // RED (no return use)
}

// ==================== GEMM: xws = dinv*(x @ Wcomb); s init; dinv store ====================
// tile: 128 rows x 64 cols, 256 threads, each thread 8 rows x 4 cols
__global__ void k_xw(const float* __restrict__ x, int n) {
    extern __shared__ float sh[];
    float* Wsm = sh;               // 128*64 = 32 KB  [k][c]
    float* Xsm = sh + F * C_OUT;   // 128*128 = 64 KB [r][k]

    int t = threadIdx.x;
    for (int i = t; i < (F * C_OUT) / 4; i += 256)
        ((float4*)Wsm)[i] = ((const float4*)g_wcomb)[i];

    int base = blockIdx.x * 128;
    for (int i = t; i < 128 * 32; i += 256) {   // 128 rows x 32 float4, coalesced
        int rr = i >> 5, cc = i & 31;
        int r = base + rr;
        float4 v = make_float4(0.f, 0.f, 0.f, 0.f);
        if (r < n) v = ((const float4*)x)[(size_t)r * 32 + cc];
        ((float4*)Xsm)[i] = v;
    }
    __syncthreads();

    int tx = t & 15;           // c0 = tx*4
    int ty = t >> 4;           // r0 = ty*8  (0..15)
    int c0 = tx * 4, r0 = ty * 8;

    float acc[8][4];
#pragma unroll
    for (int i = 0; i < 8; ++i)
#pragma unroll
        for (int j = 0; j < 4; ++j) acc[i][j] = 0.f;

#pragma unroll 4
    for (int k = 0; k < F; ++k) {
        float4 w = *(const float4*)&Wsm[k * C_OUT + c0];
#pragma unroll
        for (int i = 0; i < 8; ++i) {
            float xv = Xsm[(r0 + i) * F + k];
            acc[i][0] = fmaf(xv, w.x, acc[i][0]);
            acc[i][1] = fmaf(xv, w.y, acc[i][1]);
            acc[i][2] = fmaf(xv, w.z, acc[i][2]);
            acc[i][3] = fmaf(xv, w.w, acc[i][3]);
        }
    }

#pragma unroll
    for (int i = 0; i < 8; ++i) {
        int r = base + r0 + i;
        if (r < n) {
            float dv = rsqrtf(g_deg[r]);
            if (tx == 0) g_dinv[r] = dv;
            float4 v;
            v.x = dv * acc[i][0];
            v.y = dv * acc[i][1];
            v.z = dv * acc[i][2];
            v.w = dv * acc[i][3];
            *(float4*)&g_xws[(size_t)r * C_OUT + c0] = v;
            *(float4*)&g_s[(size_t)r * C_OUT + c0]   = v;   // self-loop init
        }
    }
}

// ==================== edge scatter: s[col] += xws[row] ====================
// 16 threads per edge, each one float4 (256 B/edge)
__global__ void k_scatter(const int* __restrict__ ei, int e) {
    int gt = blockIdx.x * blockDim.x + threadIdx.x;
    int edge = gt >> 4;
    int lane = gt & 15;
    if (edge >= e) return;
    int row = __ldg(&ei[edge]);
    int col = __ldg(&ei[e + edge]);
    float4 v = *(const float4*)&g_xws[(size_t)row * C_OUT + lane * 4];
    float* p = &g_s[(size_t)col * C_OUT + lane * 4];
    asm volatile("red.global.add.v4.f32 [%0], {%1, %2, %3, %4};"
                 :: "l"(p), "f"(v.x), "f"(v.y), "f"(v.z), "f"(v.w) : "memory");
}

// ==================== final: out = dinv * s + bfc2 ====================
__global__ void k_final(float* __restrict__ out, int n) {
    int i = blockIdx.x * blockDim.x + threadIdx.x;   // over n*16 float4s
    if (i >= n * 16) return;
    int r = i >> 4, c4 = i & 15;
    float dv = g_dinv[r];
    float4 s = ((const float4*)g_s)[i];
    float4 b = ((const float4*)g_bfc2)[c4];
    float4 o;
    o.x = fmaf(dv, s.x, b.x);
    o.y = fmaf(dv, s.y, b.y);
    o.z = fmaf(dv, s.z, b.z);
    o.w = fmaf(dv, s.w, b.w);
    ((float4*)out)[i] = o;
}

// ==================== launch ====================
extern "C" void kernel_launch(void* const* d_in, const int* in_sizes, int n_in,
                              void* d_out, int out_size) {
    const float* x    = (const float*)d_in[0];
    const int*   ei   = (const int*)d_in[1];
    const float* Wgcn = (const float*)d_in[2];
    const float* bgcn = (const float*)d_in[3];
    const float* Wfc  = (const float*)d_in[4];
    const float* bfc  = (const float*)d_in[5];
    float* out = (float*)d_out;

    int n = in_sizes[0] / F;       // 100000
    int e = in_sizes[1] / 2;       // 1600000

    static bool attr_set = false;
    if (!attr_set) {
        cudaFuncSetAttribute(k_xw, cudaFuncAttributeMaxDynamicSharedMemorySize,
                             (F * C_OUT + 128 * F) * 4);
        attr_set = true;
    }

    k_setup<<<NB_INIT + 1024 + 1, 256>>>(Wgcn, Wfc, bgcn, bfc, n);
    k_edge_deg<<<(e + 255) / 256, 256>>>(ei + e, e);

    int gemm_blocks = (n + 127) / 128;
    k_xw<<<gemm_blocks, 256, (F * C_OUT + 128 * F) * 4>>>(x, n);

    int sthreads = e * 16;
    k_scatter<<<(sthreads + 255) / 256, 256>>>(ei, e);

    k_final<<<(n * 16 + 255) / 256, 256>>>(out, n);
}

// round 5
// speedup vs baseline: 2.8162x; 1.0767x over previous
#include <cuda_runtime.h>
#include <cstdint>

#define N_NODES 100000
#define E_EDGES 1600000
#define F       128
#define C_OUT   64

// ---- device scratch ----
__device__ float g_deg[N_NODES];
__device__ float g_dinv[N_NODES];
__device__ float g_wcomb[F * C_OUT];             // W_gcn @ W_fc^T  [128][64]
__device__ float g_xws[(size_t)N_NODES * C_OUT]; // dinv * (x @ Wcomb)  (25.6 MB)
__device__ float g_s[(size_t)N_NODES * C_OUT];   // scatter accumulator (25.6 MB)
__device__ float g_bfc2[C_OUT];                  // b_fc + W_fc @ b_gcn

// ==================== fused setup ====================
// blocks [0, NB_INIT)            : g_deg = 1.0
// blocks [NB_INIT, NB_INIT+1024) : wcomb, 1 warp per output, coalesced + shfl
// block  NB_INIT+1024            : bfc2
#define NB_INIT ((N_NODES + 255) / 256)

__global__ void k_setup(const float* __restrict__ Wg, const float* __restrict__ Wfc,
                        const float* __restrict__ bgcn, const float* __restrict__ bfc,
                        int n) {
    int b = blockIdx.x;
    int t = threadIdx.x;
    if (b < NB_INIT) {
        int i = b * 256 + t;
        if (i < n) g_deg[i] = 1.0f;   // self-loop
        return;
    }
    int lane = t & 31;
    int w = t >> 5;
    if (b < NB_INIT + 1024) {
        // wcomb[k][c] = sum_j Wg[k][j] * Wfc[c][j];  8 warps/block, 1 output/warp
        int idx = (b - NB_INIT) * 8 + w;      // 0..8191
        int k = idx >> 6, c = idx & 63;
        const float* wg = Wg + k * F;
        const float* wf = Wfc + c * F;
        float s = wg[lane] * wf[lane];
        s = fmaf(wg[lane + 32], wf[lane + 32], s);
        s = fmaf(wg[lane + 64], wf[lane + 64], s);
        s = fmaf(wg[lane + 96], wf[lane + 96], s);
#pragma unroll
        for (int o = 16; o > 0; o >>= 1) s += __shfl_xor_sync(0xffffffffu, s, o);
        if (lane == 0) g_wcomb[idx] = s;
        return;
    }
    // bfc2: 8 warps, 8 outputs each
#pragma unroll
    for (int cc = 0; cc < 8; ++cc) {
        int c = w * 8 + cc;
        const float* wf = Wfc + c * F;
        float s = bgcn[lane] * wf[lane];
        s = fmaf(bgcn[lane + 32], wf[lane + 32], s);
        s = fmaf(bgcn[lane + 64], wf[lane + 64], s);
        s = fmaf(bgcn[lane + 96], wf[lane + 96], s);
#pragma unroll
        for (int o = 16; o > 0; o >>= 1) s += __shfl_xor_sync(0xffffffffu, s, o);
        if (lane == 0) g_bfc2[c] = s + bfc[c];
    }
}

// ==================== degree (edges), int4 vectorized ====================
__global__ void k_edge_deg(const int* __restrict__ col, int e) {
    int i = blockIdx.x * blockDim.x + threadIdx.x;   // over e/4 int4s
    int base = i * 4;
    if (base >= e) return;
    if (base + 3 < e) {
        int4 c = *(const int4*)&col[base];
        atomicAdd(&g_deg[c.x], 1.0f);
        atomicAdd(&g_deg[c.y], 1.0f);
        atomicAdd(&g_deg[c.z], 1.0f);
        atomicAdd(&g_deg[c.w], 1.0f);
    } else {
        for (int j = base; j < e; ++j) atomicAdd(&g_deg[col[j]], 1.0f);
    }
}

// ==================== GEMM: xws = dinv*(x @ Wcomb); s init; dinv store ====================
// tile: 128 rows x 64 cols, 256 threads, each thread 8 rows x 4 cols
__global__ void k_xw(const float* __restrict__ x, int n) {
    extern __shared__ float sh[];
    float* Wsm = sh;               // 128*64 = 32 KB  [k][c]
    float* Xsm = sh + F * C_OUT;   // 128*128 = 64 KB [r][k]

    int t = threadIdx.x;
    for (int i = t; i < (F * C_OUT) / 4; i += 256)
        ((float4*)Wsm)[i] = ((const float4*)g_wcomb)[i];

    int base = blockIdx.x * 128;
    for (int i = t; i < 128 * 32; i += 256) {   // 128 rows x 32 float4, coalesced
        int rr = i >> 5, cc = i & 31;
        int r = base + rr;
        float4 v = make_float4(0.f, 0.f, 0.f, 0.f);
        if (r < n) v = ((const float4*)x)[(size_t)r * 32 + cc];
        ((float4*)Xsm)[i] = v;
    }
    __syncthreads();

    int tx = t & 15;           // c0 = tx*4
    int ty = t >> 4;           // r0 = ty*8  (0..15)
    int c0 = tx * 4, r0 = ty * 8;

    float acc[8][4];
#pragma unroll
    for (int i = 0; i < 8; ++i)
#pragma unroll
        for (int j = 0; j < 4; ++j) acc[i][j] = 0.f;

#pragma unroll 4
    for (int k = 0; k < F; ++k) {
        float4 w = *(const float4*)&Wsm[k * C_OUT + c0];
#pragma unroll
        for (int i = 0; i < 8; ++i) {
            float xv = Xsm[(r0 + i) * F + k];
            acc[i][0] = fmaf(xv, w.x, acc[i][0]);
            acc[i][1] = fmaf(xv, w.y, acc[i][1]);
            acc[i][2] = fmaf(xv, w.z, acc[i][2]);
            acc[i][3] = fmaf(xv, w.w, acc[i][3]);
        }
    }

#pragma unroll
    for (int i = 0; i < 8; ++i) {
        int r = base + r0 + i;
        if (r < n) {
            float dv = rsqrtf(g_deg[r]);
            if (tx == 0) g_dinv[r] = dv;
            float4 v;
            v.x = dv * acc[i][0];
            v.y = dv * acc[i][1];
            v.z = dv * acc[i][2];
            v.w = dv * acc[i][3];
            *(float4*)&g_xws[(size_t)r * C_OUT + c0] = v;
            *(float4*)&g_s[(size_t)r * C_OUT + c0]   = v;   // self-loop init
        }
    }
}

// ==================== edge scatter: s[col] += xws[row] ====================
// 256 threads/block process 32 edges: group g = t>>4 handles edges (eb+2g, eb+2g+1),
// lane16 = t&15 handles one float4 slot of each. int2 index loads serve both edges.
__global__ void k_scatter(const int* __restrict__ ei, int e) {
    int t = threadIdx.x;
    int ep = blockIdx.x * 32 + (t >> 4) * 2;   // even edge-pair base
    if (ep >= e) return;
    int l4 = (t & 15) * 4;

    int2 rows = *(const int2*)&ei[ep];        // ep even -> 8B aligned
    int2 cols = *(const int2*)&ei[e + ep];    // e even  -> 8B aligned

    float4 v0 = *(const float4*)&g_xws[(size_t)rows.x * C_OUT + l4];
    bool has2 = (ep + 1 < e);
    float4 v1 = has2 ? *(const float4*)&g_xws[(size_t)rows.y * C_OUT + l4]
                     : make_float4(0.f, 0.f, 0.f, 0.f);

    float* p0 = &g_s[(size_t)cols.x * C_OUT + l4];
    asm volatile("red.global.add.v4.f32 [%0], {%1, %2, %3, %4};"
                 :: "l"(p0), "f"(v0.x), "f"(v0.y), "f"(v0.z), "f"(v0.w) : "memory");
    if (has2) {
        float* p1 = &g_s[(size_t)cols.y * C_OUT + l4];
        asm volatile("red.global.add.v4.f32 [%0], {%1, %2, %3, %4};"
                     :: "l"(p1), "f"(v1.x), "f"(v1.y), "f"(v1.z), "f"(v1.w) : "memory");
    }
}

// ==================== final: out = dinv * s + bfc2 ====================
__global__ void k_final(float* __restrict__ out, int n) {
    int i = blockIdx.x * blockDim.x + threadIdx.x;   // over n*16 float4s
    if (i >= n * 16) return;
    int r = i >> 4, c4 = i & 15;
    float dv = g_dinv[r];
    float4 s = ((const float4*)g_s)[i];
    float4 b = ((const float4*)g_bfc2)[c4];
    float4 o;
    o.x = fmaf(dv, s.x, b.x);
    o.y = fmaf(dv, s.y, b.y);
    o.z = fmaf(dv, s.z, b.z);
    o.w = fmaf(dv, s.w, b.w);
    ((float4*)out)[i] = o;
}

// ==================== launch ====================
extern "C" void kernel_launch(void* const* d_in, const int* in_sizes, int n_in,
                              void* d_out, int out_size) {
    const float* x    = (const float*)d_in[0];
    const int*   ei   = (const int*)d_in[1];
    const float* Wgcn = (const float*)d_in[2];
    const float* bgcn = (const float*)d_in[3];
    const float* Wfc  = (const float*)d_in[4];
    const float* bfc  = (const float*)d_in[5];
    float* out = (float*)d_out;

    int n = in_sizes[0] / F;       // 100000
    int e = in_sizes[1] / 2;       // 1600000

    static bool attr_set = false;
    if (!attr_set) {
        cudaFuncSetAttribute(k_xw, cudaFuncAttributeMaxDynamicSharedMemorySize,
                             (F * C_OUT + 128 * F) * 4);
        attr_set = true;
    }

    k_setup<<<NB_INIT + 1024 + 1, 256>>>(Wgcn, Wfc, bgcn, bfc, n);

    int deg_threads = (e + 3) / 4;
    k_edge_deg<<<(deg_threads + 255) / 256, 256>>>(ei + e, e);

    int gemm_blocks = (n + 127) / 128;
    k_xw<<<gemm_blocks, 256, (F * C_OUT + 128 * F) * 4>>>(x, n);

    int sblocks = (e + 31) / 32;    // 32 edges per block
    k_scatter<<<sblocks, 256>>>(ei, e);

    k_final<<<(n * 16 + 255) / 256, 256>>>(out, n);
}

// round 6
// speedup vs baseline: 3.3690x; 1.1963x over previous
#include <cuda_runtime.h>
#include <cstdint>

#define N_NODES 100000
#define E_EDGES 1600000
#define F       128
#define C_OUT   64

// ---- device scratch ----
__device__ int   g_cnt[N_NODES];                 // in-degree histogram (excl. self)
__device__ int   g_ptr[N_NODES + 1];             // CSR row pointers (by target)
__device__ int   g_pos[N_NODES];                 // fill cursors
__device__ int   g_bsum[256];
__device__ int   g_boff[256];
__device__ int   g_csr[E_EDGES];                 // source node per CSR slot (6.4 MB)
__device__ float g_dinv[N_NODES];
__device__ float g_wcomb[F * C_OUT];             // W_gcn @ W_fc^T
__device__ float g_xws[(size_t)N_NODES * C_OUT]; // dinv * (x @ Wcomb)  (25.6 MB)
__device__ float g_bfc2[C_OUT];                  // b_fc + W_fc @ b_gcn

// ==================== fused setup: wcomb + bfc2 + zero cnt ====================
// blocks [0,1024): wcomb (1 warp/output).  block 1024: bfc2.  blocks >1024: zero g_cnt.
__global__ void k_setup(const float* __restrict__ Wg, const float* __restrict__ Wfc,
                        const float* __restrict__ bgcn, const float* __restrict__ bfc,
                        int n) {
    int b = blockIdx.x;
    int t = threadIdx.x;
    int lane = t & 31;
    int w = t >> 5;
    if (b < 1024) {
        int idx = b * 8 + w;                  // 0..8191
        int k = idx >> 6, c = idx & 63;
        const float* wg = Wg + k * F;
        const float* wf = Wfc + c * F;
        float s = wg[lane] * wf[lane];
        s = fmaf(wg[lane + 32], wf[lane + 32], s);
        s = fmaf(wg[lane + 64], wf[lane + 64], s);
        s = fmaf(wg[lane + 96], wf[lane + 96], s);
#pragma unroll
        for (int o = 16; o > 0; o >>= 1) s += __shfl_xor_sync(0xffffffffu, s, o);
        if (lane == 0) g_wcomb[idx] = s;
        return;
    }
    if (b == 1024) {
#pragma unroll
        for (int cc = 0; cc < 8; ++cc) {
            int c = w * 8 + cc;
            const float* wf = Wfc + c * F;
            float s = bgcn[lane] * wf[lane];
            s = fmaf(bgcn[lane + 32], wf[lane + 32], s);
            s = fmaf(bgcn[lane + 64], wf[lane + 64], s);
            s = fmaf(bgcn[lane + 96], wf[lane + 96], s);
#pragma unroll
            for (int o = 16; o > 0; o >>= 1) s += __shfl_xor_sync(0xffffffffu, s, o);
            if (lane == 0) g_bfc2[c] = s + bfc[c];
        }
        return;
    }
    // zero g_cnt: 1024 ints per block
    int base = (b - 1025) * 1024 + t * 4;
    if (base + 3 < n) *(int4*)&g_cnt[base] = make_int4(0, 0, 0, 0);
    else for (int j = base; j < n; ++j) g_cnt[j] = 0;
}

// ==================== histogram over targets ====================
__global__ void k_hist(const int* __restrict__ col, int e) {
    int base = (blockIdx.x * blockDim.x + threadIdx.x) * 4;
    if (base >= e) return;
    if (base + 3 < e) {
        int4 c = *(const int4*)&col[base];
        atomicAdd(&g_cnt[c.x], 1);
        atomicAdd(&g_cnt[c.y], 1);
        atomicAdd(&g_cnt[c.z], 1);
        atomicAdd(&g_cnt[c.w], 1);
    } else {
        for (int j = base; j < e; ++j) atomicAdd(&g_cnt[col[j]], 1);
    }
}

// ==================== exclusive scan (3 kernels) ====================
__global__ void k_scan1(int n) {
    __shared__ int wsh[8];
    __shared__ int woff[8];
    int t = threadIdx.x, b = blockIdx.x;
    int base = b * 1024 + t * 4;
    int x0 = 0, x1 = 0, x2 = 0, x3 = 0;
    if (base + 3 < n) {
        int4 v = *(const int4*)&g_cnt[base];
        x0 = v.x; x1 = v.y; x2 = v.z; x3 = v.w;
    } else if (base < n) {
        x0 = g_cnt[base];
        if (base + 1 < n) x1 = g_cnt[base + 1];
        if (base + 2 < n) x2 = g_cnt[base + 2];
    }
    int s0 = x0, s1 = s0 + x1, s2 = s1 + x2, s3 = s2 + x3;
    int lane = t & 31, w = t >> 5;
    int ws = s3;
#pragma unroll
    for (int o = 1; o < 32; o <<= 1) {
        int u = __shfl_up_sync(0xffffffffu, ws, o);
        if (lane >= o) ws += u;
    }
    if (lane == 31) wsh[w] = ws;
    __syncthreads();
    if (t == 0) {
        int acc = 0;
#pragma unroll
        for (int i = 0; i < 8; ++i) { woff[i] = acc; acc += wsh[i]; }
        g_bsum[b] = acc;
    }
    __syncthreads();
    int excl = woff[w] + ws - s3;
    if (base < n)     g_ptr[base]     = excl;
    if (base + 1 < n) g_ptr[base + 1] = excl + s0;
    if (base + 2 < n) g_ptr[base + 2] = excl + s1;
    if (base + 3 < n) g_ptr[base + 3] = excl + s2;
}

__global__ void k_scan2(int nb) {
    __shared__ int wsh[8];
    __shared__ int woff[8];
    int t = threadIdx.x;
    int v = (t < nb) ? g_bsum[t] : 0;
    int lane = t & 31, w = t >> 5;
    int ws = v;
#pragma unroll
    for (int o = 1; o < 32; o <<= 1) {
        int u = __shfl_up_sync(0xffffffffu, ws, o);
        if (lane >= o) ws += u;
    }
    if (lane == 31) wsh[w] = ws;
    __syncthreads();
    if (t == 0) {
        int acc = 0;
#pragma unroll
        for (int i = 0; i < 8; ++i) { woff[i] = acc; acc += wsh[i]; }
    }
    __syncthreads();
    if (t < nb) g_boff[t] = woff[w] + ws - v;
}

__global__ void k_scan3(int n, int e) {
    int t = threadIdx.x, b = blockIdx.x;
    int off = g_boff[b];
    int base = b * 1024 + t * 4;
#pragma unroll
    for (int j = 0; j < 4; ++j) {
        int i = base + j;
        if (i < n) {
            int p = g_ptr[i] + off;
            g_ptr[i] = p;
            g_pos[i] = p;
            g_dinv[i] = rsqrtf((float)(g_cnt[i] + 1));
        }
    }
    if (b == 0 && t == 0) g_ptr[n] = e;
}

// ==================== CSR fill: bucket source rows by target ====================
__global__ void k_fill(const int* __restrict__ ei, int e) {
    int i = (blockIdx.x * blockDim.x + threadIdx.x) * 2;
    if (i >= e) return;
    int2 rows = *(const int2*)&ei[i];       // i even -> 8B aligned
    int2 cols = *(const int2*)&ei[e + i];   // e even -> 8B aligned
    int p0 = atomicAdd(&g_pos[cols.x], 1);
    g_csr[p0] = rows.x;
    if (i + 1 < e) {
        int p1 = atomicAdd(&g_pos[cols.y], 1);
        g_csr[p1] = rows.y;
    }
}

// ==================== GEMM: xws = dinv * (x @ Wcomb) ====================
// tile: 128 rows x 64 cols, 256 threads, each thread 8 rows x 4 cols
__global__ void k_xw(const float* __restrict__ x, int n) {
    extern __shared__ float sh[];
    float* Wsm = sh;               // 128*64 = 32 KB  [k][c]
    float* Xsm = sh + F * C_OUT;   // 128*128 = 64 KB [r][k]

    int t = threadIdx.x;
    for (int i = t; i < (F * C_OUT) / 4; i += 256)
        ((float4*)Wsm)[i] = ((const float4*)g_wcomb)[i];

    int base = blockIdx.x * 128;
    for (int i = t; i < 128 * 32; i += 256) {
        int rr = i >> 5, cc = i & 31;
        int r = base + rr;
        float4 v = make_float4(0.f, 0.f, 0.f, 0.f);
        if (r < n) v = ((const float4*)x)[(size_t)r * 32 + cc];
        ((float4*)Xsm)[i] = v;
    }
    __syncthreads();

    int tx = t & 15;
    int ty = t >> 4;
    int c0 = tx * 4, r0 = ty * 8;

    float acc[8][4];
#pragma unroll
    for (int i = 0; i < 8; ++i)
#pragma unroll
        for (int j = 0; j < 4; ++j) acc[i][j] = 0.f;

#pragma unroll 4
    for (int k = 0; k < F; ++k) {
        float4 w = *(const float4*)&Wsm[k * C_OUT + c0];
#pragma unroll
        for (int i = 0; i < 8; ++i) {
            float xv = Xsm[(r0 + i) * F + k];
            acc[i][0] = fmaf(xv, w.x, acc[i][0]);
            acc[i][1] = fmaf(xv, w.y, acc[i][1]);
            acc[i][2] = fmaf(xv, w.z, acc[i][2]);
            acc[i][3] = fmaf(xv, w.w, acc[i][3]);
        }
    }

#pragma unroll
    for (int i = 0; i < 8; ++i) {
        int r = base + r0 + i;
        if (r < n) {
            float dv = g_dinv[r];
            float4 v;
            v.x = dv * acc[i][0];
            v.y = dv * acc[i][1];
            v.z = dv * acc[i][2];
            v.w = dv * acc[i][3];
            *(float4*)&g_xws[(size_t)r * C_OUT + c0] = v;
        }
    }
}

// ==================== gather + epilogue: out = dinv*(self + sum nbrs) + bfc2 ====================
// 16 threads per node, each owns one float4 column slot
__global__ void k_gather(float* __restrict__ out, int n) {
    int gt = blockIdx.x * blockDim.x + threadIdx.x;
    int r = gt >> 4;
    if (r >= n) return;
    int l4 = (gt & 15) * 4;

    int p0 = __ldg(&g_ptr[r]);
    int p1 = __ldg(&g_ptr[r + 1]);

    float4 acc = *(const float4*)&g_xws[(size_t)r * C_OUT + l4];  // self-loop

    int j = p0;
    int nxt = (j < p1) ? __ldg(&g_csr[j]) : 0;
    while (j < p1) {
        int idx = nxt;
        ++j;
        nxt = (j < p1) ? __ldg(&g_csr[j]) : 0;
        float4 v = *(const float4*)&g_xws[(size_t)idx * C_OUT + l4];
        acc.x += v.x; acc.y += v.y; acc.z += v.z; acc.w += v.w;
    }

    float dv = __ldg(&g_dinv[r]);
    float4 b = *(const float4*)&g_bfc2[l4];
    float4 o;
    o.x = fmaf(dv, acc.x, b.x);
    o.y = fmaf(dv, acc.y, b.y);
    o.z = fmaf(dv, acc.z, b.z);
    o.w = fmaf(dv, acc.w, b.w);
    *(float4*)&out[(size_t)r * C_OUT + l4] = o;
}

// ==================== launch ====================
extern "C" void kernel_launch(void* const* d_in, const int* in_sizes, int n_in,
                              void* d_out, int out_size) {
    const float* x    = (const float*)d_in[0];
    const int*   ei   = (const int*)d_in[1];
    const float* Wgcn = (const float*)d_in[2];
    const float* bgcn = (const float*)d_in[3];
    const float* Wfc  = (const float*)d_in[4];
    const float* bfc  = (const float*)d_in[5];
    float* out = (float*)d_out;

    int n = in_sizes[0] / F;       // 100000
    int e = in_sizes[1] / 2;       // 1600000

    static bool attr_set = false;
    if (!attr_set) {
        cudaFuncSetAttribute(k_xw, cudaFuncAttributeMaxDynamicSharedMemorySize,
                             (F * C_OUT + 128 * F) * 4);
        attr_set = true;
    }

    int nbs = (n + 1023) / 1024;                       // scan blocks (98)

    k_setup<<<1024 + 1 + nbs, 256>>>(Wgcn, Wfc, bgcn, bfc, n);

    int hthreads = (e + 3) / 4;
    k_hist<<<(hthreads + 255) / 256, 256>>>(ei + e, e);

    k_scan1<<<nbs, 256>>>(n);
    k_scan2<<<1, 256>>>(nbs);
    k_scan3<<<nbs, 256>>>(n, e);

    int gemm_blocks = (n + 127) / 128;
    k_xw<<<gemm_blocks, 256, (F * C_OUT + 128 * F) * 4>>>(x, n);

    int fthreads = (e + 1) / 2;
    k_fill<<<(fthreads + 255) / 256, 256>>>(ei, e);

    k_gather<<<(n * 16 + 255) / 256, 256>>>(out, n);
}